// round 5
// baseline (speedup 1.0000x reference)
#include <cuda_runtime.h>
#include <cstdint>
#include <cstddef>

// Problem constants (fixed by setup_inputs)
#define BB   8
#define LL   4096
#define DD   1024
#define HH   16
#define HD   64
#define MROWS (BB * LL)          // 32768
#define GK   1024
#define GN   1024

// ---------------------------------------------------------------------------
// Scratch (allocation-free rule: __device__ globals)
// ---------------------------------------------------------------------------
__device__ float g_xq[(size_t)MROWS * DD];
__device__ float g_xk[(size_t)MROWS * DD];
__device__ float g_xv[(size_t)MROWS * DD];
__device__ float g_ctx[(size_t)MROWS * DD];

// ---------------------------------------------------------------------------
// Packed f32x2 helpers (sm_100+): 2x fp32 FMA throughput on the fma pipe.
// ---------------------------------------------------------------------------
__device__ __forceinline__ unsigned long long pack_dup(float a) {
    unsigned long long r;
    asm("mov.b64 %0, {%1, %1};" : "=l"(r) : "f"(a));
    return r;
}
__device__ __forceinline__ void fma2(unsigned long long& d,
                                     unsigned long long a,
                                     unsigned long long b) {
    asm("fma.rn.f32x2 %0, %1, %2, %0;" : "+l"(d) : "l"(a), "l"(b));
}
__device__ __forceinline__ float lo32(unsigned long long v) {
    return __uint_as_float((unsigned)(v & 0xffffffffu));
}
__device__ __forceinline__ float hi32(unsigned long long v) {
    return __uint_as_float((unsigned)(v >> 32));
}

// ---------------------------------------------------------------------------
// SGEMM with bias: C[M,1024] = A[M,1024] @ W[1024,1024] + bias
// BM=BN=128, BK=8, 256 threads, 8x8 microtile via f32x2 pairs.
// M, N, K all divisible by tile sizes -> no bounds checks.
// ---------------------------------------------------------------------------
__global__ __launch_bounds__(256, 2)
void sgemm_bias_kernel(const float* __restrict__ A,
                       const float* __restrict__ W,
                       const float* __restrict__ bias,
                       float* __restrict__ C) {
    const int bx  = blockIdx.x;          // N tile (0..7)
    const int by  = blockIdx.y;          // M tile (0..255)
    const int tid = threadIdx.x;
    const int tx  = tid & 15;            // 0..15 (N micro)
    const int ty  = tid >> 4;            // 0..15 (M micro)

    __shared__ float As[8][128];         // [k][m] (transposed A tile)
    __shared__ float Bs[8][128];         // [k][n]

    const int row0 = by * 128;
    const int col0 = bx * 128;

    // Load assignments
    const int aRow = tid >> 1;           // 0..127
    const int aCol = (tid & 1) * 4;      // 0 or 4
    const int bRow = tid >> 5;           // 0..7
    const int bCol = (tid & 31) * 4;     // 0..124

    const float* Aptr = A + (size_t)(row0 + aRow) * GK + aCol;
    const float* Wptr = W + (size_t)bRow * GN + col0 + bCol;

    unsigned long long acc[8][4];
#pragma unroll
    for (int i = 0; i < 8; i++)
#pragma unroll
        for (int j = 0; j < 4; j++) acc[i][j] = 0ULL;

    // Prefetch first tile into registers
    float4 aReg = *(const float4*)Aptr;
    float4 bReg = *(const float4*)Wptr;

    const int NT = GK / 8;               // 128 k-tiles
    for (int t = 0; t < NT; ++t) {
        // Stage registers -> smem
        As[aCol + 0][aRow] = aReg.x;
        As[aCol + 1][aRow] = aReg.y;
        As[aCol + 2][aRow] = aReg.z;
        As[aCol + 3][aRow] = aReg.w;
        *(float4*)&Bs[bRow][bCol] = bReg;
        __syncthreads();

        // Prefetch next tile (hide LDG latency under compute)
        if (t + 1 < NT) {
            aReg = *(const float4*)(Aptr + (size_t)(t + 1) * 8);
            bReg = *(const float4*)(Wptr + (size_t)(t + 1) * 8 * GN);
        }

#pragma unroll
        for (int k = 0; k < 8; ++k) {
            float4 a0 = *(const float4*)&As[k][ty * 8];
            float4 a1 = *(const float4*)&As[k][ty * 8 + 4];
            ulonglong2 b01 = *(const ulonglong2*)&Bs[k][tx * 8];
            ulonglong2 b23 = *(const ulonglong2*)&Bs[k][tx * 8 + 4];

            unsigned long long ap[8];
            ap[0] = pack_dup(a0.x); ap[1] = pack_dup(a0.y);
            ap[2] = pack_dup(a0.z); ap[3] = pack_dup(a0.w);
            ap[4] = pack_dup(a1.x); ap[5] = pack_dup(a1.y);
            ap[6] = pack_dup(a1.z); ap[7] = pack_dup(a1.w);

            unsigned long long bp[4] = {b01.x, b01.y, b23.x, b23.y};
#pragma unroll
            for (int i = 0; i < 8; ++i)
#pragma unroll
                for (int j = 0; j < 4; ++j) fma2(acc[i][j], ap[i], bp[j]);
        }
        __syncthreads();
    }

    // Epilogue: add bias, write 8x8 tile
    const float* bpt = bias + col0 + tx * 8;
    const float4 bv0 = *(const float4*)bpt;
    const float4 bv1 = *(const float4*)(bpt + 4);

#pragma unroll
    for (int i = 0; i < 8; ++i) {
        float4 o0, o1;
        o0.x = lo32(acc[i][0]) + bv0.x;
        o0.y = hi32(acc[i][0]) + bv0.y;
        o0.z = lo32(acc[i][1]) + bv0.z;
        o0.w = hi32(acc[i][1]) + bv0.w;
        o1.x = lo32(acc[i][2]) + bv1.x;
        o1.y = hi32(acc[i][2]) + bv1.y;
        o1.z = lo32(acc[i][3]) + bv1.z;
        o1.w = hi32(acc[i][3]) + bv1.w;
        float* cp = C + (size_t)(row0 + ty * 8 + i) * GN + col0 + tx * 8;
        *(float4*)cp       = o0;
        *(float4*)(cp + 4) = o1;
    }
}

// ---------------------------------------------------------------------------
// Head-axis attention, one CTA per (b, g) where g = l/16 covers 16 positions.
// Faithful to the "view(B, n_head, L, hd)" reshape:
//   Q[b,l,h,e] = Xq[b, h*256 + l/16, (l%16)*64 + e]
// ctx is written back in the same scrambled layout (pre-transpose/reshape),
// weights written in natural (B, L, H, H) layout.
// ---------------------------------------------------------------------------
__global__ __launch_bounds__(256)
void attn_kernel(const float4* __restrict__ Xq,
                 const float4* __restrict__ Xk,
                 const float4* __restrict__ Xv,
                 float4* __restrict__ Ctx,
                 float4* __restrict__ Wout) {
    const int g = blockIdx.x;  // 0..255
    const int b = blockIdx.y;  // 0..7

    extern __shared__ float sm[];
    float4* Qs = (float4*)sm;          // 16 rows x 256 float4
    float4* Ks = Qs + 4096;
    float4* Vs = Ks + 4096;
    float*  Ws = (float*)(Vs + 4096);  // 16 pos x 16 x 16

    const int tid = threadIdx.x;

    // Stage 16 scattered rows of each tensor (row h -> global row b*4096 + h*256 + g)
    for (int i = tid; i < 4096; i += 256) {
        int h  = i >> 8;
        int cv = i & 255;
        size_t gi = ((size_t)(b * LL + h * 256 + g)) * 256 + cv;
        Qs[i] = Xq[gi];
        Ks[i] = Xk[gi];
        Vs[i] = Xv[gi];
    }
    __syncthreads();

    const int c  = tid >> 4;   // position within group (0..15)
    const int hh = tid & 15;   // head row (0..15) for S phase / e-slice for ctx

    // ---- S = scale * Q K^T, softmax over j (full row lives in one thread) ----
    float4 qr[16];
#pragma unroll
    for (int e = 0; e < 16; ++e) qr[e] = Qs[hh * 256 + c * 16 + e];

    float s[16];
#pragma unroll
    for (int j = 0; j < 16; ++j) {
        float acc = 0.f;
#pragma unroll
        for (int e = 0; e < 16; ++e) {
            float4 kv = Ks[j * 256 + c * 16 + e];
            acc += qr[e].x * kv.x + qr[e].y * kv.y + qr[e].z * kv.z + qr[e].w * kv.w;
        }
        s[j] = acc * 0.125f;   // hd^-0.5 = 1/8
    }

    float m = s[0];
#pragma unroll
    for (int j = 1; j < 16; ++j) m = fmaxf(m, s[j]);
    float sum = 0.f;
#pragma unroll
    for (int j = 0; j < 16; ++j) { s[j] = expf(s[j] - m); sum += s[j]; }
    float inv = 1.f / sum;
#pragma unroll
    for (int j = 0; j < 16; ++j) s[j] *= inv;

    // Stash weights in smem for the ctx phase + write to global (B, L, H, H)
#pragma unroll
    for (int j = 0; j < 16; ++j) Ws[(c * 16 + hh) * 16 + j] = s[j];

    {
        float4* wp = Wout + ((size_t)((b * LL + g * 16 + c) * 16 + hh)) * 4;
        wp[0] = make_float4(s[0],  s[1],  s[2],  s[3]);
        wp[1] = make_float4(s[4],  s[5],  s[6],  s[7]);
        wp[2] = make_float4(s[8],  s[9],  s[10], s[11]);
        wp[3] = make_float4(s[12], s[13], s[14], s[15]);
    }
    __syncthreads();

    // ---- ctx[h][e] = sum_j W[h][j] * V[j][e]; thread owns 4 e's for all h ----
    const int sidx = hh;  // float4 column slice within this position
    float4 vr[16];
#pragma unroll
    for (int j = 0; j < 16; ++j) vr[j] = Vs[j * 256 + c * 16 + sidx];

#pragma unroll
    for (int h2 = 0; h2 < 16; ++h2) {
        float4 acc = make_float4(0.f, 0.f, 0.f, 0.f);
#pragma unroll
        for (int j = 0; j < 16; ++j) {
            float w = Ws[(c * 16 + h2) * 16 + j];
            acc.x += w * vr[j].x;
            acc.y += w * vr[j].y;
            acc.z += w * vr[j].z;
            acc.w += w * vr[j].w;
        }
        Ctx[((size_t)(b * LL + h2 * 256 + g)) * 256 + c * 16 + sidx] = acc;
    }
}

// ---------------------------------------------------------------------------
// Launch: 3 projection GEMMs -> attention -> output GEMM.
// Inputs (metadata order): q,k,v,Wq,bq,Wk,bk,Wv,bv,Wo,bo,(n_head)
// Output: [out (B*L*D) | weights (B*L*H*H)]
// ---------------------------------------------------------------------------
extern "C" void kernel_launch(void* const* d_in, const int* in_sizes, int n_in,
                              void* d_out, int out_size) {
    const float* q  = (const float*)d_in[0];
    const float* k  = (const float*)d_in[1];
    const float* v  = (const float*)d_in[2];
    const float* Wq = (const float*)d_in[3];
    const float* bq = (const float*)d_in[4];
    const float* Wk = (const float*)d_in[5];
    const float* bk = (const float*)d_in[6];
    const float* Wv = (const float*)d_in[7];
    const float* bv = (const float*)d_in[8];
    const float* Wo = (const float*)d_in[9];
    const float* bo = (const float*)d_in[10];

    float* out = (float*)d_out;
    float* wts = out + (size_t)MROWS * DD;

    float *xq, *xk, *xv, *ctx;
    cudaGetSymbolAddress((void**)&xq,  g_xq);
    cudaGetSymbolAddress((void**)&xk,  g_xk);
    cudaGetSymbolAddress((void**)&xv,  g_xv);
    cudaGetSymbolAddress((void**)&ctx, g_ctx);

    const int ATTN_SMEM = (3 * 4096 * 16) + (4096 * 4);  // 212992 bytes
    cudaFuncSetAttribute(attn_kernel,
                         cudaFuncAttributeMaxDynamicSharedMemorySize, ATTN_SMEM);

    dim3 gGemm(GN / 128, MROWS / 128);   // (8, 256)
    sgemm_bias_kernel<<<gGemm, 256>>>(q, Wq, bq, xq);
    sgemm_bias_kernel<<<gGemm, 256>>>(k, Wk, bk, xk);
    sgemm_bias_kernel<<<gGemm, 256>>>(v, Wv, bv, xv);

    dim3 gAttn(LL / 16, BB);             // (256, 8)
    attn_kernel<<<gAttn, 256, ATTN_SMEM>>>((const float4*)xq, (const float4*)xk,
                                           (const float4*)xv, (float4*)ctx,
                                           (float4*)wts);

    sgemm_bias_kernel<<<gGemm, 256>>>(ctx, Wo, bo, out);
}

// round 6
// speedup vs baseline: 1.0012x; 1.0012x over previous
#include <cuda_runtime.h>
#include <cstdint>
#include <cstddef>

// Problem constants (fixed by setup_inputs)
#define BB   8
#define LL   4096
#define DD   1024
#define HH   16
#define HD   64
#define MROWS (BB * LL)          // 32768
#define GK   1024
#define GN   1024

// ---------------------------------------------------------------------------
// Scratch (allocation-free rule: __device__ globals)
// ---------------------------------------------------------------------------
__device__ float g_xq[(size_t)MROWS * DD];
__device__ float g_xk[(size_t)MROWS * DD];
__device__ float g_xv[(size_t)MROWS * DD];
__device__ float g_ctx[(size_t)MROWS * DD];

// ---------------------------------------------------------------------------
// Packed f32x2 helpers (sm_100+): 2x fp32 FMA throughput on the fma pipe.
// ---------------------------------------------------------------------------
__device__ __forceinline__ unsigned long long pack_dup(float a) {
    unsigned long long r;
    asm("mov.b64 %0, {%1, %1};" : "=l"(r) : "f"(a));
    return r;
}
__device__ __forceinline__ void fma2(unsigned long long& d,
                                     unsigned long long a,
                                     unsigned long long b) {
    asm("fma.rn.f32x2 %0, %1, %2, %0;" : "+l"(d) : "l"(a), "l"(b));
}
__device__ __forceinline__ float lo32(unsigned long long v) {
    return __uint_as_float((unsigned)(v & 0xffffffffu));
}
__device__ __forceinline__ float hi32(unsigned long long v) {
    return __uint_as_float((unsigned)(v >> 32));
}

// ---------------------------------------------------------------------------
// SGEMM with bias: C[M,1024] = A[M,1024] @ W[1024,1024] + bias
// BM=BN=128, BK=8, 256 threads, 8x8 microtile via f32x2 pairs.
// M, N, K all divisible by tile sizes -> no bounds checks.
// ---------------------------------------------------------------------------
__global__ __launch_bounds__(256, 2)
void sgemm_bias_kernel(const float* __restrict__ A,
                       const float* __restrict__ W,
                       const float* __restrict__ bias,
                       float* __restrict__ C) {
    const int bx  = blockIdx.x;          // N tile (0..7)
    const int by  = blockIdx.y;          // M tile (0..255)
    const int tid = threadIdx.x;
    const int tx  = tid & 15;            // 0..15 (N micro)
    const int ty  = tid >> 4;            // 0..15 (M micro)

    __shared__ float As[8][128];         // [k][m] (transposed A tile)
    __shared__ float Bs[8][128];         // [k][n]

    const int row0 = by * 128;
    const int col0 = bx * 128;

    // Load assignments
    const int aRow = tid >> 1;           // 0..127
    const int aCol = (tid & 1) * 4;      // 0 or 4
    const int bRow = tid >> 5;           // 0..7
    const int bCol = (tid & 31) * 4;     // 0..124

    const float* Aptr = A + (size_t)(row0 + aRow) * GK + aCol;
    const float* Wptr = W + (size_t)bRow * GN + col0 + bCol;

    unsigned long long acc[8][4];
#pragma unroll
    for (int i = 0; i < 8; i++)
#pragma unroll
        for (int j = 0; j < 4; j++) acc[i][j] = 0ULL;

    // Prefetch first tile into registers
    float4 aReg = *(const float4*)Aptr;
    float4 bReg = *(const float4*)Wptr;

    const int NT = GK / 8;               // 128 k-tiles
    for (int t = 0; t < NT; ++t) {
        // Stage registers -> smem
        As[aCol + 0][aRow] = aReg.x;
        As[aCol + 1][aRow] = aReg.y;
        As[aCol + 2][aRow] = aReg.z;
        As[aCol + 3][aRow] = aReg.w;
        *(float4*)&Bs[bRow][bCol] = bReg;
        __syncthreads();

        // Prefetch next tile (hide LDG latency under compute)
        if (t + 1 < NT) {
            aReg = *(const float4*)(Aptr + (size_t)(t + 1) * 8);
            bReg = *(const float4*)(Wptr + (size_t)(t + 1) * 8 * GN);
        }

#pragma unroll
        for (int k = 0; k < 8; ++k) {
            float4 a0 = *(const float4*)&As[k][ty * 8];
            float4 a1 = *(const float4*)&As[k][ty * 8 + 4];
            ulonglong2 b01 = *(const ulonglong2*)&Bs[k][tx * 8];
            ulonglong2 b23 = *(const ulonglong2*)&Bs[k][tx * 8 + 4];

            unsigned long long ap[8];
            ap[0] = pack_dup(a0.x); ap[1] = pack_dup(a0.y);
            ap[2] = pack_dup(a0.z); ap[3] = pack_dup(a0.w);
            ap[4] = pack_dup(a1.x); ap[5] = pack_dup(a1.y);
            ap[6] = pack_dup(a1.z); ap[7] = pack_dup(a1.w);

            unsigned long long bp[4] = {b01.x, b01.y, b23.x, b23.y};
#pragma unroll
            for (int i = 0; i < 8; ++i)
#pragma unroll
                for (int j = 0; j < 4; ++j) fma2(acc[i][j], ap[i], bp[j]);
        }
        __syncthreads();
    }

    // Epilogue: add bias, write 8x8 tile
    const float* bpt = bias + col0 + tx * 8;
    const float4 bv0 = *(const float4*)bpt;
    const float4 bv1 = *(const float4*)(bpt + 4);

#pragma unroll
    for (int i = 0; i < 8; ++i) {
        float4 o0, o1;
        o0.x = lo32(acc[i][0]) + bv0.x;
        o0.y = hi32(acc[i][0]) + bv0.y;
        o0.z = lo32(acc[i][1]) + bv0.z;
        o0.w = hi32(acc[i][1]) + bv0.w;
        o1.x = lo32(acc[i][2]) + bv1.x;
        o1.y = hi32(acc[i][2]) + bv1.y;
        o1.z = lo32(acc[i][3]) + bv1.z;
        o1.w = hi32(acc[i][3]) + bv1.w;
        float* cp = C + (size_t)(row0 + ty * 8 + i) * GN + col0 + tx * 8;
        *(float4*)cp       = o0;
        *(float4*)(cp + 4) = o1;
    }
}

// ---------------------------------------------------------------------------
// Head-axis attention, one CTA per (b, g) where g = l/16 covers 16 positions.
// Faithful to the "view(B, n_head, L, hd)" reshape:
//   Q[b,l,h,e] = Xq[b, h*256 + l/16, (l%16)*64 + e]
// ctx is written back in the same scrambled layout (pre-transpose/reshape),
// weights written in natural (B, L, H, H) layout.
// ---------------------------------------------------------------------------
__global__ __launch_bounds__(256)
void attn_kernel(const float4* __restrict__ Xq,
                 const float4* __restrict__ Xk,
                 const float4* __restrict__ Xv,
                 float4* __restrict__ Ctx,
                 float4* __restrict__ Wout) {
    const int g = blockIdx.x;  // 0..255
    const int b = blockIdx.y;  // 0..7

    extern __shared__ float sm[];
    float4* Qs = (float4*)sm;          // 16 rows x 256 float4
    float4* Ks = Qs + 4096;
    float4* Vs = Ks + 4096;
    float*  Ws = (float*)(Vs + 4096);  // 16 pos x 16 x 16

    const int tid = threadIdx.x;

    // Stage 16 scattered rows of each tensor (row h -> global row b*4096 + h*256 + g)
    for (int i = tid; i < 4096; i += 256) {
        int h  = i >> 8;
        int cv = i & 255;
        size_t gi = ((size_t)(b * LL + h * 256 + g)) * 256 + cv;
        Qs[i] = Xq[gi];
        Ks[i] = Xk[gi];
        Vs[i] = Xv[gi];
    }
    __syncthreads();

    const int c  = tid >> 4;   // position within group (0..15)
    const int hh = tid & 15;   // head row (0..15) for S phase / e-slice for ctx

    // ---- S = scale * Q K^T, softmax over j (full row lives in one thread) ----
    float4 qr[16];
#pragma unroll
    for (int e = 0; e < 16; ++e) qr[e] = Qs[hh * 256 + c * 16 + e];

    float s[16];
#pragma unroll
    for (int j = 0; j < 16; ++j) {
        float acc = 0.f;
#pragma unroll
        for (int e = 0; e < 16; ++e) {
            float4 kv = Ks[j * 256 + c * 16 + e];
            acc += qr[e].x * kv.x + qr[e].y * kv.y + qr[e].z * kv.z + qr[e].w * kv.w;
        }
        s[j] = acc * 0.125f;   // hd^-0.5 = 1/8
    }

    float m = s[0];
#pragma unroll
    for (int j = 1; j < 16; ++j) m = fmaxf(m, s[j]);
    float sum = 0.f;
#pragma unroll
    for (int j = 0; j < 16; ++j) { s[j] = expf(s[j] - m); sum += s[j]; }
    float inv = 1.f / sum;
#pragma unroll
    for (int j = 0; j < 16; ++j) s[j] *= inv;

    // Stash weights in smem for the ctx phase + write to global (B, L, H, H)
#pragma unroll
    for (int j = 0; j < 16; ++j) Ws[(c * 16 + hh) * 16 + j] = s[j];

    {
        float4* wp = Wout + ((size_t)((b * LL + g * 16 + c) * 16 + hh)) * 4;
        wp[0] = make_float4(s[0],  s[1],  s[2],  s[3]);
        wp[1] = make_float4(s[4],  s[5],  s[6],  s[7]);
        wp[2] = make_float4(s[8],  s[9],  s[10], s[11]);
        wp[3] = make_float4(s[12], s[13], s[14], s[15]);
    }
    __syncthreads();

    // ---- ctx[h][e] = sum_j W[h][j] * V[j][e]; thread owns 4 e's for all h ----
    const int sidx = hh;  // float4 column slice within this position
    float4 vr[16];
#pragma unroll
    for (int j = 0; j < 16; ++j) vr[j] = Vs[j * 256 + c * 16 + sidx];

#pragma unroll
    for (int h2 = 0; h2 < 16; ++h2) {
        float4 acc = make_float4(0.f, 0.f, 0.f, 0.f);
#pragma unroll
        for (int j = 0; j < 16; ++j) {
            float w = Ws[(c * 16 + h2) * 16 + j];
            acc.x += w * vr[j].x;
            acc.y += w * vr[j].y;
            acc.z += w * vr[j].z;
            acc.w += w * vr[j].w;
        }
        Ctx[((size_t)(b * LL + h2 * 256 + g)) * 256 + c * 16 + sidx] = acc;
    }
}

// ---------------------------------------------------------------------------
// Launch: 3 projection GEMMs -> attention -> output GEMM.
// Inputs (metadata order): q,k,v,Wq,bq,Wk,bk,Wv,bv,Wo,bo,(n_head)
// Output: [out (B*L*D) | weights (B*L*H*H)]
// ---------------------------------------------------------------------------
extern "C" void kernel_launch(void* const* d_in, const int* in_sizes, int n_in,
                              void* d_out, int out_size) {
    const float* q  = (const float*)d_in[0];
    const float* k  = (const float*)d_in[1];
    const float* v  = (const float*)d_in[2];
    const float* Wq = (const float*)d_in[3];
    const float* bq = (const float*)d_in[4];
    const float* Wk = (const float*)d_in[5];
    const float* bk = (const float*)d_in[6];
    const float* Wv = (const float*)d_in[7];
    const float* bv = (const float*)d_in[8];
    const float* Wo = (const float*)d_in[9];
    const float* bo = (const float*)d_in[10];

    float* out = (float*)d_out;
    float* wts = out + (size_t)MROWS * DD;

    float *xq, *xk, *xv, *ctx;
    cudaGetSymbolAddress((void**)&xq,  g_xq);
    cudaGetSymbolAddress((void**)&xk,  g_xk);
    cudaGetSymbolAddress((void**)&xv,  g_xv);
    cudaGetSymbolAddress((void**)&ctx, g_ctx);

    const int ATTN_SMEM = (3 * 4096 * 16) + (4096 * 4);  // 212992 bytes
    cudaFuncSetAttribute(attn_kernel,
                         cudaFuncAttributeMaxDynamicSharedMemorySize, ATTN_SMEM);

    dim3 gGemm(GN / 128, MROWS / 128);   // (8, 256)
    sgemm_bias_kernel<<<gGemm, 256>>>(q, Wq, bq, xq);
    sgemm_bias_kernel<<<gGemm, 256>>>(k, Wk, bk, xk);
    sgemm_bias_kernel<<<gGemm, 256>>>(v, Wv, bv, xv);

    dim3 gAttn(LL / 16, BB);             // (256, 8)
    attn_kernel<<<gAttn, 256, ATTN_SMEM>>>((const float4*)xq, (const float4*)xk,
                                           (const float4*)xv, (float4*)ctx,
                                           (float4*)wts);

    sgemm_bias_kernel<<<gGemm, 256>>>(ctx, Wo, bo, out);
}

// round 8
// speedup vs baseline: 2.2814x; 2.2787x over previous
#include <cuda_runtime.h>
#include <cuda_bf16.h>
#include <mma.h>
#include <cstdint>
#include <cstddef>

using namespace nvcuda;

// Problem constants (fixed by setup_inputs)
#define BB   8
#define LL   4096
#define DD   1024
#define HH   16
#define MROWS (BB * LL)          // 32768

// ---------------------------------------------------------------------------
// Scratch (allocation-free rule: __device__ globals)
// ---------------------------------------------------------------------------
__device__ __align__(1024) float g_xq[(size_t)MROWS * DD];
__device__ __align__(1024) float g_xk[(size_t)MROWS * DD];
__device__ __align__(1024) float g_xv[(size_t)MROWS * DD];
__device__ __align__(1024) float g_ctx[(size_t)MROWS * DD];
// bf16 split operands: A hi/lo row-major [32768][1024]
__device__ __align__(1024) __nv_bfloat16 g_Ah[(size_t)MROWS * DD];
__device__ __align__(1024) __nv_bfloat16 g_Al[(size_t)MROWS * DD];
// W transposed hi/lo: Bt[n][k] = W[k][n], row-major [1024][1024], 4 matrices
__device__ __align__(1024) __nv_bfloat16 g_Wh[4][(size_t)DD * DD];
__device__ __align__(1024) __nv_bfloat16 g_Wl[4][(size_t)DD * DD];

// ---------------------------------------------------------------------------
// Helpers
// ---------------------------------------------------------------------------
__device__ __forceinline__ uint32_t smem_to_u32(const void* p) {
    uint32_t a;
    asm("{ .reg .u64 t; cvta.to.shared.u64 t, %1; cvt.u32.u64 %0, t; }"
        : "=r"(a) : "l"(p));
    return a;
}
__device__ __forceinline__ void cp_async16(uint32_t dst, const void* src) {
    asm volatile("cp.async.cg.shared.global [%0], [%1], 16;"
                 :: "r"(dst), "l"(src) : "memory");
}
__device__ __forceinline__ void cp_commit() {
    asm volatile("cp.async.commit_group;" ::: "memory");
}
template <int N>
__device__ __forceinline__ void cp_wait() {
    asm volatile("cp.async.wait_group %0;" :: "n"(N) : "memory");
}

__device__ __forceinline__ void split_bf16(float x, __nv_bfloat16& h, __nv_bfloat16& l) {
    h = __float2bfloat16_rn(x);
    l = __float2bfloat16_rn(x - __bfloat162float(h));
}

// ---------------------------------------------------------------------------
// Convert A (fp32 [32768,1024]) -> hi/lo bf16 row-major. 8 floats/thread.
// ---------------------------------------------------------------------------
__global__ __launch_bounds__(256)
void conv_a_kernel(const float4* __restrict__ A,
                   __nv_bfloat16* __restrict__ Hi,
                   __nv_bfloat16* __restrict__ Lo) {
    size_t i = (size_t)blockIdx.x * 256 + threadIdx.x;   // 8-float group index
    float4 x0 = A[i * 2];
    float4 x1 = A[i * 2 + 1];
    float xs[8] = {x0.x, x0.y, x0.z, x0.w, x1.x, x1.y, x1.z, x1.w};
    __nv_bfloat16 h[8], l[8];
#pragma unroll
    for (int j = 0; j < 8; ++j) split_bf16(xs[j], h[j], l[j]);
    *(uint4*)(Hi + i * 8) = *(const uint4*)h;
    *(uint4*)(Lo + i * 8) = *(const uint4*)l;
}

// ---------------------------------------------------------------------------
// Convert + transpose W (fp32 [1024,1024]) -> Bt hi/lo [n][k] bf16.
// 32x32 smem tile transpose, 256 threads (32x,8y).
// ---------------------------------------------------------------------------
__global__ __launch_bounds__(256)
void conv_w_kernel(const float* __restrict__ W,
                   __nv_bfloat16* __restrict__ Hi,
                   __nv_bfloat16* __restrict__ Lo) {
    __shared__ float t[32][33];
    const int tx = threadIdx.x & 31;
    const int ty = threadIdx.x >> 5;        // 0..7
    const int n0 = blockIdx.x * 32, k0 = blockIdx.y * 32;
#pragma unroll
    for (int j = 0; j < 4; ++j)
        t[ty + 8 * j][tx] = W[(size_t)(k0 + ty + 8 * j) * DD + n0 + tx];
    __syncthreads();
#pragma unroll
    for (int j = 0; j < 4; ++j) {
        float v = t[tx][ty + 8 * j];        // = W[k0+tx][n0+ty+8j]
        __nv_bfloat16 h, l;
        split_bf16(v, h, l);
        size_t o = (size_t)(n0 + ty + 8 * j) * DD + k0 + tx;
        Hi[o] = h;
        Lo[o] = l;
    }
}

// ---------------------------------------------------------------------------
// wmma bf16 GEMM (3-pass hi/lo split): C = A @ W + bias.
// BM=BN=128, BK=32, 8 warps (4m x 2n), warp tile 32x64 (2x4 wmma frags).
// 2-stage cp.async pipeline. Smem rows padded to 48 bf16 (96B, 16B-aligned).
// ---------------------------------------------------------------------------
#define STAGE_ELEMS 6144                    // 128*48 bf16 per matrix image
#define STAGE_BYTES 49152                   // 4 matrix images * 12288B
#define GEMM_SMEM   (2 * STAGE_BYTES)       // 98304B (epilogue reuses it)

__global__ __launch_bounds__(256, 2)
void gemm_wmma_kernel(const __nv_bfloat16* __restrict__ Ah,
                      const __nv_bfloat16* __restrict__ Al,
                      const __nv_bfloat16* __restrict__ Bh,
                      const __nv_bfloat16* __restrict__ Bl,
                      const float* __restrict__ bias,
                      float* __restrict__ C) {
    extern __shared__ __align__(128) uint8_t smem[];
    const uint32_t sb = smem_to_u32(smem);
    const int tid = threadIdx.x;
    const int wid = tid >> 5;
    const int wm = wid & 3;                 // 0..3 -> 32-row strip
    const int wn = wid >> 2;                // 0..1 -> 64-col strip
    const int nt = blockIdx.x, mt = blockIdx.y;
    const int row0 = mt * 128, col0 = nt * 128;

    wmma::fragment<wmma::accumulator, 16, 16, 16, float> acc[2][4];
#pragma unroll
    for (int i = 0; i < 2; ++i)
#pragma unroll
        for (int j = 0; j < 4; ++j) wmma::fill_fragment(acc[i][j], 0.0f);

    // --- stage loader: 8 cp.async/thread (2 chunks x 4 matrix images) ---
    const int c0row = (tid * 2) >> 3;       // chunk pair: rows tid*2/8.. pattern
    // simpler explicit mapping below
#define LOAD_STAGE(t, s) do {                                               \
    const int k0 = (t) * 32;                                                \
    uint32_t st = sb + (uint32_t)(s) * STAGE_BYTES;                         \
    _Pragma("unroll")                                                       \
    for (int h = 0; h < 2; ++h) {                                           \
        int c   = tid + h * 256;            /* 0..511 */                    \
        int row = c >> 2;                   /* 0..127 */                    \
        int q   = (c & 3) * 8;              /* k offset 0,8,16,24 */        \
        uint32_t doff = (uint32_t)(row * 48 + q) * 2;                       \
        size_t aoff = (size_t)(row0 + row) * DD + k0 + q;                   \
        size_t boff = (size_t)(col0 + row) * DD + k0 + q;                   \
        cp_async16(st + doff,                  Ah + aoff);                  \
        cp_async16(st + 12288u + doff,         Al + aoff);                  \
        cp_async16(st + 24576u + doff,         Bh + boff);                  \
        cp_async16(st + 36864u + doff,         Bl + boff);                  \
    }                                                                       \
} while (0)

    LOAD_STAGE(0, 0);
    cp_commit();

    for (int t = 0; t < 32; ++t) {
        const int s = t & 1;
        if (t + 1 < 32) {
            LOAD_STAGE(t + 1, s ^ 1);
            cp_commit();
            cp_wait<1>();
        } else {
            cp_wait<0>();
        }
        __syncthreads();

        const __nv_bfloat16* sAh = (const __nv_bfloat16*)(smem + s * STAGE_BYTES);
        const __nv_bfloat16* sAl = sAh + STAGE_ELEMS;
        const __nv_bfloat16* sBh = sAh + 2 * STAGE_ELEMS;
        const __nv_bfloat16* sBl = sAh + 3 * STAGE_ELEMS;

#pragma unroll
        for (int ks = 0; ks < 2; ++ks) {
            const int ko = ks * 16;
            wmma::fragment<wmma::matrix_a, 16, 16, 16, __nv_bfloat16,
                           wmma::row_major> a_h[2], a_l[2];
#pragma unroll
            for (int i = 0; i < 2; ++i) {
                const int r = (wm * 32 + i * 16) * 48 + ko;
                wmma::load_matrix_sync(a_h[i], sAh + r, 48);
                wmma::load_matrix_sync(a_l[i], sAl + r, 48);
            }
#pragma unroll
            for (int j = 0; j < 4; ++j) {
                wmma::fragment<wmma::matrix_b, 16, 16, 16, __nv_bfloat16,
                               wmma::col_major> b_h, b_l;
                const int r = (wn * 64 + j * 16) * 48 + ko;
                wmma::load_matrix_sync(b_h, sBh + r, 48);
                wmma::load_matrix_sync(b_l, sBl + r, 48);
#pragma unroll
                for (int i = 0; i < 2; ++i) {
                    wmma::mma_sync(acc[i][j], a_h[i], b_h, acc[i][j]);
                    wmma::mma_sync(acc[i][j], a_h[i], b_l, acc[i][j]);
                    wmma::mma_sync(acc[i][j], a_l[i], b_h, acc[i][j]);
                }
            }
        }
        __syncthreads();
    }
#undef LOAD_STAGE

    // --- epilogue: acc -> smem (128x132 f32) -> coalesced bias-add stores ---
    float* cs = (float*)smem;
#pragma unroll
    for (int i = 0; i < 2; ++i)
#pragma unroll
        for (int j = 0; j < 4; ++j)
            wmma::store_matrix_sync(cs + (wm * 32 + i * 16) * 132 + wn * 64 + j * 16,
                                    acc[i][j], 132, wmma::mem_row_major);
    __syncthreads();

#pragma unroll
    for (int it = 0; it < 16; ++it) {
        int idx = tid + it * 256;            // 4096 float4 groups
        int r   = idx >> 5;                  // 0..127
        int c4  = (idx & 31) * 4;            // 0..124
        float4 bv = *(const float4*)(bias + col0 + c4);
        float4 o;
        o.x = cs[r * 132 + c4 + 0] + bv.x;
        o.y = cs[r * 132 + c4 + 1] + bv.y;
        o.z = cs[r * 132 + c4 + 2] + bv.z;
        o.w = cs[r * 132 + c4 + 3] + bv.w;
        *(float4*)(C + (size_t)(row0 + r) * DD + col0 + c4) = o;
    }
}

// ---------------------------------------------------------------------------
// Head-axis attention (unchanged — 255us).
// ---------------------------------------------------------------------------
__global__ __launch_bounds__(256)
void attn_kernel(const float4* __restrict__ Xq,
                 const float4* __restrict__ Xk,
                 const float4* __restrict__ Xv,
                 float4* __restrict__ Ctx,
                 float4* __restrict__ Wout) {
    const int g = blockIdx.x;
    const int b = blockIdx.y;

    extern __shared__ float sm[];
    float4* Qs = (float4*)sm;
    float4* Ks = Qs + 4096;
    float4* Vs = Ks + 4096;
    float*  Ws = (float*)(Vs + 4096);

    const int tid = threadIdx.x;

    for (int i = tid; i < 4096; i += 256) {
        int h  = i >> 8;
        int cv = i & 255;
        size_t gi = ((size_t)(b * LL + h * 256 + g)) * 256 + cv;
        Qs[i] = Xq[gi];
        Ks[i] = Xk[gi];
        Vs[i] = Xv[gi];
    }
    __syncthreads();

    const int c  = tid >> 4;
    const int hh = tid & 15;

    float4 qr[16];
#pragma unroll
    for (int e = 0; e < 16; ++e) qr[e] = Qs[hh * 256 + c * 16 + e];

    float s[16];
#pragma unroll
    for (int j = 0; j < 16; ++j) {
        float acc = 0.f;
#pragma unroll
        for (int e = 0; e < 16; ++e) {
            float4 kv = Ks[j * 256 + c * 16 + e];
            acc += qr[e].x * kv.x + qr[e].y * kv.y + qr[e].z * kv.z + qr[e].w * kv.w;
        }
        s[j] = acc * 0.125f;
    }

    float m = s[0];
#pragma unroll
    for (int j = 1; j < 16; ++j) m = fmaxf(m, s[j]);
    float sum = 0.f;
#pragma unroll
    for (int j = 0; j < 16; ++j) { s[j] = expf(s[j] - m); sum += s[j]; }
    float inv = 1.f / sum;
#pragma unroll
    for (int j = 0; j < 16; ++j) s[j] *= inv;

#pragma unroll
    for (int j = 0; j < 16; ++j) Ws[(c * 16 + hh) * 16 + j] = s[j];

    {
        float4* wp = Wout + ((size_t)((b * LL + g * 16 + c) * 16 + hh)) * 4;
        wp[0] = make_float4(s[0],  s[1],  s[2],  s[3]);
        wp[1] = make_float4(s[4],  s[5],  s[6],  s[7]);
        wp[2] = make_float4(s[8],  s[9],  s[10], s[11]);
        wp[3] = make_float4(s[12], s[13], s[14], s[15]);
    }
    __syncthreads();

    const int sidx = hh;
    float4 vr[16];
#pragma unroll
    for (int j = 0; j < 16; ++j) vr[j] = Vs[j * 256 + c * 16 + sidx];

#pragma unroll
    for (int h2 = 0; h2 < 16; ++h2) {
        float4 acc = make_float4(0.f, 0.f, 0.f, 0.f);
#pragma unroll
        for (int j = 0; j < 16; ++j) {
            float w = Ws[(c * 16 + h2) * 16 + j];
            acc.x += w * vr[j].x;
            acc.y += w * vr[j].y;
            acc.z += w * vr[j].z;
            acc.w += w * vr[j].w;
        }
        Ctx[((size_t)(b * LL + h2 * 256 + g)) * 256 + c * 16 + sidx] = acc;
    }
}

// ---------------------------------------------------------------------------
// Launch sequence
// ---------------------------------------------------------------------------
extern "C" void kernel_launch(void* const* d_in, const int* in_sizes, int n_in,
                              void* d_out, int out_size) {
    const float* q  = (const float*)d_in[0];
    const float* k  = (const float*)d_in[1];
    const float* v  = (const float*)d_in[2];
    const float* Wq = (const float*)d_in[3];
    const float* bq = (const float*)d_in[4];
    const float* Wk = (const float*)d_in[5];
    const float* bk = (const float*)d_in[6];
    const float* Wv = (const float*)d_in[7];
    const float* bv = (const float*)d_in[8];
    const float* Wo = (const float*)d_in[9];
    const float* bo = (const float*)d_in[10];

    float* out = (float*)d_out;
    float* wts = out + (size_t)MROWS * DD;

    float *xq, *xk, *xv, *ctx;
    __nv_bfloat16 *ah, *al, *wh, *wl;
    cudaGetSymbolAddress((void**)&xq,  g_xq);
    cudaGetSymbolAddress((void**)&xk,  g_xk);
    cudaGetSymbolAddress((void**)&xv,  g_xv);
    cudaGetSymbolAddress((void**)&ctx, g_ctx);
    cudaGetSymbolAddress((void**)&ah,  g_Ah);
    cudaGetSymbolAddress((void**)&al,  g_Al);
    cudaGetSymbolAddress((void**)&wh,  g_Wh);
    cudaGetSymbolAddress((void**)&wl,  g_Wl);

    const size_t WSZ = (size_t)DD * DD;
    __nv_bfloat16* wh4[4] = {wh, wh + WSZ, wh + 2 * WSZ, wh + 3 * WSZ};
    __nv_bfloat16* wl4[4] = {wl, wl + WSZ, wl + 2 * WSZ, wl + 3 * WSZ};
    const float* Ws4[4] = {Wq, Wk, Wv, Wo};

    const int ATTN_SMEM = (3 * 4096 * 16) + (4096 * 4);
    cudaFuncSetAttribute(attn_kernel,
                         cudaFuncAttributeMaxDynamicSharedMemorySize, ATTN_SMEM);
    cudaFuncSetAttribute(gemm_wmma_kernel,
                         cudaFuncAttributeMaxDynamicSharedMemorySize, GEMM_SMEM);

    dim3 gW(32, 32);                         // conv_w: 32x32 tiles
    dim3 gA(MROWS * DD / 8 / 256);           // conv_a: 16384 blocks
    dim3 gG(8, 256);                         // gemm: 8 n-tiles x 256 m-tiles
    dim3 gAt(LL / 16, BB);

    for (int i = 0; i < 4; ++i)
        conv_w_kernel<<<gW, 256>>>(Ws4[i], wh4[i], wl4[i]);

    conv_a_kernel<<<gA, 256>>>((const float4*)q, ah, al);
    gemm_wmma_kernel<<<gG, 256, GEMM_SMEM>>>(ah, al, wh4[0], wl4[0], bq, xq);

    conv_a_kernel<<<gA, 256>>>((const float4*)k, ah, al);
    gemm_wmma_kernel<<<gG, 256, GEMM_SMEM>>>(ah, al, wh4[1], wl4[1], bk, xk);

    conv_a_kernel<<<gA, 256>>>((const float4*)v, ah, al);
    gemm_wmma_kernel<<<gG, 256, GEMM_SMEM>>>(ah, al, wh4[2], wl4[2], bv, xv);

    attn_kernel<<<gAt, 256, ATTN_SMEM>>>((const float4*)xq, (const float4*)xk,
                                         (const float4*)xv, (float4*)ctx,
                                         (float4*)wts);

    conv_a_kernel<<<gA, 256>>>((const float4*)ctx, ah, al);
    gemm_wmma_kernel<<<gG, 256, GEMM_SMEM>>>(ah, al, wh4[3], wl4[3], bo, out);
}

// round 9
// speedup vs baseline: 2.2816x; 1.0001x over previous
#include <cuda_runtime.h>
#include <cuda_bf16.h>
#include <mma.h>
#include <cstdint>
#include <cstddef>

using namespace nvcuda;

// Problem constants (fixed by setup_inputs)
#define BB   8
#define LL   4096
#define DD   1024
#define HH   16
#define MROWS (BB * LL)          // 32768

// ---------------------------------------------------------------------------
// Scratch (allocation-free rule: __device__ globals)
// ---------------------------------------------------------------------------
__device__ __align__(1024) float g_xq[(size_t)MROWS * DD];
__device__ __align__(1024) float g_xk[(size_t)MROWS * DD];
__device__ __align__(1024) float g_xv[(size_t)MROWS * DD];
__device__ __align__(1024) float g_ctx[(size_t)MROWS * DD];
// bf16 split operands: A hi/lo row-major [32768][1024]
__device__ __align__(1024) __nv_bfloat16 g_Ah[(size_t)MROWS * DD];
__device__ __align__(1024) __nv_bfloat16 g_Al[(size_t)MROWS * DD];
// W transposed hi/lo: Bt[n][k] = W[k][n], row-major [1024][1024], 4 matrices
__device__ __align__(1024) __nv_bfloat16 g_Wh[4][(size_t)DD * DD];
__device__ __align__(1024) __nv_bfloat16 g_Wl[4][(size_t)DD * DD];

// ---------------------------------------------------------------------------
// Helpers
// ---------------------------------------------------------------------------
__device__ __forceinline__ uint32_t smem_to_u32(const void* p) {
    uint32_t a;
    asm("{ .reg .u64 t; cvta.to.shared.u64 t, %1; cvt.u32.u64 %0, t; }"
        : "=r"(a) : "l"(p));
    return a;
}
__device__ __forceinline__ void cp_async16(uint32_t dst, const void* src) {
    asm volatile("cp.async.cg.shared.global [%0], [%1], 16;"
                 :: "r"(dst), "l"(src) : "memory");
}
__device__ __forceinline__ void cp_commit() {
    asm volatile("cp.async.commit_group;" ::: "memory");
}
template <int N>
__device__ __forceinline__ void cp_wait() {
    asm volatile("cp.async.wait_group %0;" :: "n"(N) : "memory");
}

__device__ __forceinline__ void split_bf16(float x, __nv_bfloat16& h, __nv_bfloat16& l) {
    h = __float2bfloat16_rn(x);
    l = __float2bfloat16_rn(x - __bfloat162float(h));
}

// ---------------------------------------------------------------------------
// Convert A (fp32 [32768,1024]) -> hi/lo bf16 row-major. 8 floats/thread.
// ---------------------------------------------------------------------------
__global__ __launch_bounds__(256)
void conv_a_kernel(const float4* __restrict__ A,
                   __nv_bfloat16* __restrict__ Hi,
                   __nv_bfloat16* __restrict__ Lo) {
    size_t i = (size_t)blockIdx.x * 256 + threadIdx.x;   // 8-float group index
    float4 x0 = A[i * 2];
    float4 x1 = A[i * 2 + 1];
    float xs[8] = {x0.x, x0.y, x0.z, x0.w, x1.x, x1.y, x1.z, x1.w};
    __nv_bfloat16 h[8], l[8];
#pragma unroll
    for (int j = 0; j < 8; ++j) split_bf16(xs[j], h[j], l[j]);
    *(uint4*)(Hi + i * 8) = *(const uint4*)h;
    *(uint4*)(Lo + i * 8) = *(const uint4*)l;
}

// ---------------------------------------------------------------------------
// Convert + transpose W (fp32 [1024,1024]) -> Bt hi/lo [n][k] bf16.
// 32x32 smem tile transpose, 256 threads (32x,8y).
// ---------------------------------------------------------------------------
__global__ __launch_bounds__(256)
void conv_w_kernel(const float* __restrict__ W,
                   __nv_bfloat16* __restrict__ Hi,
                   __nv_bfloat16* __restrict__ Lo) {
    __shared__ float t[32][33];
    const int tx = threadIdx.x & 31;
    const int ty = threadIdx.x >> 5;        // 0..7
    const int n0 = blockIdx.x * 32, k0 = blockIdx.y * 32;
#pragma unroll
    for (int j = 0; j < 4; ++j)
        t[ty + 8 * j][tx] = W[(size_t)(k0 + ty + 8 * j) * DD + n0 + tx];
    __syncthreads();
#pragma unroll
    for (int j = 0; j < 4; ++j) {
        float v = t[tx][ty + 8 * j];        // = W[k0+tx][n0+ty+8j]
        __nv_bfloat16 h, l;
        split_bf16(v, h, l);
        size_t o = (size_t)(n0 + ty + 8 * j) * DD + k0 + tx;
        Hi[o] = h;
        Lo[o] = l;
    }
}

// ---------------------------------------------------------------------------
// wmma bf16 GEMM (3-pass hi/lo split): C = A @ W + bias.
// BM=BN=128, BK=32, 8 warps (4m x 2n), warp tile 32x64 (2x4 wmma frags).
// 2-stage cp.async pipeline. Smem rows padded to 48 bf16 (96B, 16B-aligned).
// ---------------------------------------------------------------------------
#define STAGE_ELEMS 6144                    // 128*48 bf16 per matrix image
#define STAGE_BYTES 49152                   // 4 matrix images * 12288B
#define GEMM_SMEM   (2 * STAGE_BYTES)       // 98304B (epilogue reuses it)

__global__ __launch_bounds__(256, 2)
void gemm_wmma_kernel(const __nv_bfloat16* __restrict__ Ah,
                      const __nv_bfloat16* __restrict__ Al,
                      const __nv_bfloat16* __restrict__ Bh,
                      const __nv_bfloat16* __restrict__ Bl,
                      const float* __restrict__ bias,
                      float* __restrict__ C) {
    extern __shared__ __align__(128) uint8_t smem[];
    const uint32_t sb = smem_to_u32(smem);
    const int tid = threadIdx.x;
    const int wid = tid >> 5;
    const int wm = wid & 3;                 // 0..3 -> 32-row strip
    const int wn = wid >> 2;                // 0..1 -> 64-col strip
    const int nt = blockIdx.x, mt = blockIdx.y;
    const int row0 = mt * 128, col0 = nt * 128;

    wmma::fragment<wmma::accumulator, 16, 16, 16, float> acc[2][4];
#pragma unroll
    for (int i = 0; i < 2; ++i)
#pragma unroll
        for (int j = 0; j < 4; ++j) wmma::fill_fragment(acc[i][j], 0.0f);

    // --- stage loader: 8 cp.async/thread (2 chunks x 4 matrix images) ---
    const int c0row = (tid * 2) >> 3;       // chunk pair: rows tid*2/8.. pattern
    // simpler explicit mapping below
#define LOAD_STAGE(t, s) do {                                               \
    const int k0 = (t) * 32;                                                \
    uint32_t st = sb + (uint32_t)(s) * STAGE_BYTES;                         \
    _Pragma("unroll")                                                       \
    for (int h = 0; h < 2; ++h) {                                           \
        int c   = tid + h * 256;            /* 0..511 */                    \
        int row = c >> 2;                   /* 0..127 */                    \
        int q   = (c & 3) * 8;              /* k offset 0,8,16,24 */        \
        uint32_t doff = (uint32_t)(row * 48 + q) * 2;                       \
        size_t aoff = (size_t)(row0 + row) * DD + k0 + q;                   \
        size_t boff = (size_t)(col0 + row) * DD + k0 + q;                   \
        cp_async16(st + doff,                  Ah + aoff);                  \
        cp_async16(st + 12288u + doff,         Al + aoff);                  \
        cp_async16(st + 24576u + doff,         Bh + boff);                  \
        cp_async16(st + 36864u + doff,         Bl + boff);                  \
    }                                                                       \
} while (0)

    LOAD_STAGE(0, 0);
    cp_commit();

    for (int t = 0; t < 32; ++t) {
        const int s = t & 1;
        if (t + 1 < 32) {
            LOAD_STAGE(t + 1, s ^ 1);
            cp_commit();
            cp_wait<1>();
        } else {
            cp_wait<0>();
        }
        __syncthreads();

        const __nv_bfloat16* sAh = (const __nv_bfloat16*)(smem + s * STAGE_BYTES);
        const __nv_bfloat16* sAl = sAh + STAGE_ELEMS;
        const __nv_bfloat16* sBh = sAh + 2 * STAGE_ELEMS;
        const __nv_bfloat16* sBl = sAh + 3 * STAGE_ELEMS;

#pragma unroll
        for (int ks = 0; ks < 2; ++ks) {
            const int ko = ks * 16;
            wmma::fragment<wmma::matrix_a, 16, 16, 16, __nv_bfloat16,
                           wmma::row_major> a_h[2], a_l[2];
#pragma unroll
            for (int i = 0; i < 2; ++i) {
                const int r = (wm * 32 + i * 16) * 48 + ko;
                wmma::load_matrix_sync(a_h[i], sAh + r, 48);
                wmma::load_matrix_sync(a_l[i], sAl + r, 48);
            }
#pragma unroll
            for (int j = 0; j < 4; ++j) {
                wmma::fragment<wmma::matrix_b, 16, 16, 16, __nv_bfloat16,
                               wmma::col_major> b_h, b_l;
                const int r = (wn * 64 + j * 16) * 48 + ko;
                wmma::load_matrix_sync(b_h, sBh + r, 48);
                wmma::load_matrix_sync(b_l, sBl + r, 48);
#pragma unroll
                for (int i = 0; i < 2; ++i) {
                    wmma::mma_sync(acc[i][j], a_h[i], b_h, acc[i][j]);
                    wmma::mma_sync(acc[i][j], a_h[i], b_l, acc[i][j]);
                    wmma::mma_sync(acc[i][j], a_l[i], b_h, acc[i][j]);
                }
            }
        }
        __syncthreads();
    }
#undef LOAD_STAGE

    // --- epilogue: acc -> smem (128x132 f32) -> coalesced bias-add stores ---
    float* cs = (float*)smem;
#pragma unroll
    for (int i = 0; i < 2; ++i)
#pragma unroll
        for (int j = 0; j < 4; ++j)
            wmma::store_matrix_sync(cs + (wm * 32 + i * 16) * 132 + wn * 64 + j * 16,
                                    acc[i][j], 132, wmma::mem_row_major);
    __syncthreads();

#pragma unroll
    for (int it = 0; it < 16; ++it) {
        int idx = tid + it * 256;            // 4096 float4 groups
        int r   = idx >> 5;                  // 0..127
        int c4  = (idx & 31) * 4;            // 0..124
        float4 bv = *(const float4*)(bias + col0 + c4);
        float4 o;
        o.x = cs[r * 132 + c4 + 0] + bv.x;
        o.y = cs[r * 132 + c4 + 1] + bv.y;
        o.z = cs[r * 132 + c4 + 2] + bv.z;
        o.w = cs[r * 132 + c4 + 3] + bv.w;
        *(float4*)(C + (size_t)(row0 + r) * DD + col0 + c4) = o;
    }
}

// ---------------------------------------------------------------------------
// Head-axis attention (unchanged — 255us).
// ---------------------------------------------------------------------------
__global__ __launch_bounds__(256)
void attn_kernel(const float4* __restrict__ Xq,
                 const float4* __restrict__ Xk,
                 const float4* __restrict__ Xv,
                 float4* __restrict__ Ctx,
                 float4* __restrict__ Wout) {
    const int g = blockIdx.x;
    const int b = blockIdx.y;

    extern __shared__ float sm[];
    float4* Qs = (float4*)sm;
    float4* Ks = Qs + 4096;
    float4* Vs = Ks + 4096;
    float*  Ws = (float*)(Vs + 4096);

    const int tid = threadIdx.x;

    for (int i = tid; i < 4096; i += 256) {
        int h  = i >> 8;
        int cv = i & 255;
        size_t gi = ((size_t)(b * LL + h * 256 + g)) * 256 + cv;
        Qs[i] = Xq[gi];
        Ks[i] = Xk[gi];
        Vs[i] = Xv[gi];
    }
    __syncthreads();

    const int c  = tid >> 4;
    const int hh = tid & 15;

    float4 qr[16];
#pragma unroll
    for (int e = 0; e < 16; ++e) qr[e] = Qs[hh * 256 + c * 16 + e];

    float s[16];
#pragma unroll
    for (int j = 0; j < 16; ++j) {
        float acc = 0.f;
#pragma unroll
        for (int e = 0; e < 16; ++e) {
            float4 kv = Ks[j * 256 + c * 16 + e];
            acc += qr[e].x * kv.x + qr[e].y * kv.y + qr[e].z * kv.z + qr[e].w * kv.w;
        }
        s[j] = acc * 0.125f;
    }

    float m = s[0];
#pragma unroll
    for (int j = 1; j < 16; ++j) m = fmaxf(m, s[j]);
    float sum = 0.f;
#pragma unroll
    for (int j = 0; j < 16; ++j) { s[j] = expf(s[j] - m); sum += s[j]; }
    float inv = 1.f / sum;
#pragma unroll
    for (int j = 0; j < 16; ++j) s[j] *= inv;

#pragma unroll
    for (int j = 0; j < 16; ++j) Ws[(c * 16 + hh) * 16 + j] = s[j];

    {
        float4* wp = Wout + ((size_t)((b * LL + g * 16 + c) * 16 + hh)) * 4;
        wp[0] = make_float4(s[0],  s[1],  s[2],  s[3]);
        wp[1] = make_float4(s[4],  s[5],  s[6],  s[7]);
        wp[2] = make_float4(s[8],  s[9],  s[10], s[11]);
        wp[3] = make_float4(s[12], s[13], s[14], s[15]);
    }
    __syncthreads();

    const int sidx = hh;
    float4 vr[16];
#pragma unroll
    for (int j = 0; j < 16; ++j) vr[j] = Vs[j * 256 + c * 16 + sidx];

#pragma unroll
    for (int h2 = 0; h2 < 16; ++h2) {
        float4 acc = make_float4(0.f, 0.f, 0.f, 0.f);
#pragma unroll
        for (int j = 0; j < 16; ++j) {
            float w = Ws[(c * 16 + h2) * 16 + j];
            acc.x += w * vr[j].x;
            acc.y += w * vr[j].y;
            acc.z += w * vr[j].z;
            acc.w += w * vr[j].w;
        }
        Ctx[((size_t)(b * LL + h2 * 256 + g)) * 256 + c * 16 + sidx] = acc;
    }
}

// ---------------------------------------------------------------------------
// Launch sequence
// ---------------------------------------------------------------------------
extern "C" void kernel_launch(void* const* d_in, const int* in_sizes, int n_in,
                              void* d_out, int out_size) {
    const float* q  = (const float*)d_in[0];
    const float* k  = (const float*)d_in[1];
    const float* v  = (const float*)d_in[2];
    const float* Wq = (const float*)d_in[3];
    const float* bq = (const float*)d_in[4];
    const float* Wk = (const float*)d_in[5];
    const float* bk = (const float*)d_in[6];
    const float* Wv = (const float*)d_in[7];
    const float* bv = (const float*)d_in[8];
    const float* Wo = (const float*)d_in[9];
    const float* bo = (const float*)d_in[10];

    float* out = (float*)d_out;
    float* wts = out + (size_t)MROWS * DD;

    float *xq, *xk, *xv, *ctx;
    __nv_bfloat16 *ah, *al, *wh, *wl;
    cudaGetSymbolAddress((void**)&xq,  g_xq);
    cudaGetSymbolAddress((void**)&xk,  g_xk);
    cudaGetSymbolAddress((void**)&xv,  g_xv);
    cudaGetSymbolAddress((void**)&ctx, g_ctx);
    cudaGetSymbolAddress((void**)&ah,  g_Ah);
    cudaGetSymbolAddress((void**)&al,  g_Al);
    cudaGetSymbolAddress((void**)&wh,  g_Wh);
    cudaGetSymbolAddress((void**)&wl,  g_Wl);

    const size_t WSZ = (size_t)DD * DD;
    __nv_bfloat16* wh4[4] = {wh, wh + WSZ, wh + 2 * WSZ, wh + 3 * WSZ};
    __nv_bfloat16* wl4[4] = {wl, wl + WSZ, wl + 2 * WSZ, wl + 3 * WSZ};
    const float* Ws4[4] = {Wq, Wk, Wv, Wo};

    const int ATTN_SMEM = (3 * 4096 * 16) + (4096 * 4);
    cudaFuncSetAttribute(attn_kernel,
                         cudaFuncAttributeMaxDynamicSharedMemorySize, ATTN_SMEM);
    cudaFuncSetAttribute(gemm_wmma_kernel,
                         cudaFuncAttributeMaxDynamicSharedMemorySize, GEMM_SMEM);

    dim3 gW(32, 32);                         // conv_w: 32x32 tiles
    dim3 gA(MROWS * DD / 8 / 256);           // conv_a: 16384 blocks
    dim3 gG(8, 256);                         // gemm: 8 n-tiles x 256 m-tiles
    dim3 gAt(LL / 16, BB);

    for (int i = 0; i < 4; ++i)
        conv_w_kernel<<<gW, 256>>>(Ws4[i], wh4[i], wl4[i]);

    conv_a_kernel<<<gA, 256>>>((const float4*)q, ah, al);
    gemm_wmma_kernel<<<gG, 256, GEMM_SMEM>>>(ah, al, wh4[0], wl4[0], bq, xq);

    conv_a_kernel<<<gA, 256>>>((const float4*)k, ah, al);
    gemm_wmma_kernel<<<gG, 256, GEMM_SMEM>>>(ah, al, wh4[1], wl4[1], bk, xk);

    conv_a_kernel<<<gA, 256>>>((const float4*)v, ah, al);
    gemm_wmma_kernel<<<gG, 256, GEMM_SMEM>>>(ah, al, wh4[2], wl4[2], bv, xv);

    attn_kernel<<<gAt, 256, ATTN_SMEM>>>((const float4*)xq, (const float4*)xk,
                                         (const float4*)xv, (float4*)ctx,
                                         (float4*)wts);

    conv_a_kernel<<<gA, 256>>>((const float4*)ctx, ah, al);
    gemm_wmma_kernel<<<gG, 256, GEMM_SMEM>>>(ah, al, wh4[3], wl4[3], bo, out);
}